// round 11
// baseline (speedup 1.0000x reference)
#include <cuda_runtime.h>
#include <math.h>

#define H 1024
#define E 48
#define R 32
#define KC 16          // k-chunks in precompute
#define KCHUNK 64      // H / KC
#define TOTROWS 128    // 48 P + 48 Q + 32 B rows
#define MROWS 8        // rows per precompute block
#define MAXITEMS (E * 6)    // worst: 47 active j -> 6 items of 8 per i

typedef unsigned long long ull;

// Combined precompute result: [0:48H) = P+b1 rows, [48H:96H) = Q rows, [96H:128H) = B rows
__device__ __align__(16) float g_PQB[TOTROWS * H];
// Per-k-chunk partials (8 MB)
__device__ __align__(16) float g_part[KC * TOTROWS * H];
// B transposed for lane=k access: BT4[h4][k] = float4{B[k][4h4..4h4+3]}
__device__ __align__(16) float4 g_BT4[(H / 4) * R];
// work queue: 8-j items
__device__ int g_itemhdr[MAXITEMS];   // i | (nj << 8)
__device__ ull g_itemjs[MAXITEMS];    // 8 j's, one byte each (padded with group j0)
__device__ int g_nitems;

// ---- packed f32x2 helpers (Blackwell) ------------------------------------
__device__ __forceinline__ ull f2fma(ull a, ull b, ull c) {
    ull d;
    asm("fma.rn.f32x2 %0, %1, %2, %3;" : "=l"(d) : "l"(a), "l"(b), "l"(c));
    return d;
}
__device__ __forceinline__ ull f2add(ull a, ull b) {
    ull d;
    asm("add.rn.f32x2 %0, %1, %2;" : "=l"(d) : "l"(a), "l"(b));
    return d;
}
__device__ __forceinline__ ull f2pack(float lo, float hi) {
    ull d;
    asm("mov.b64 %0, {%1, %2};" : "=l"(d) : "f"(lo), "f"(hi));
    return d;
}
__device__ __forceinline__ void f2unpack(ull v, float& lo, float& hi) {
    asm("mov.b64 {%0, %1}, %2;" : "=f"(lo), "=f"(hi) : "l"(v));
}
// packed relu: max each half against 0 (FMNMX on aliased halves)
__device__ __forceinline__ ull f2relu(ull v) {
    float lo, hi;
    f2unpack(v, lo, hi);
    lo = fmaxf(lo, 0.f);
    hi = fmaxf(hi, 0.f);
    return f2pack(lo, hi);
}

// ---------------------------------------------------------------------------
// Kernel 1: partial GEMMs (R6 winner, verbatim). 4 cols/thread, LDG.128
// double-buffered W prefetch, grid (32, 16), 128 threads.
// ---------------------------------------------------------------------------
__global__ void __launch_bounds__(128, 5)
precompute_kernel(const float* __restrict__ ent,
                  const float* __restrict__ rel,
                  const float* __restrict__ W1)
{
    __shared__ __align__(16) ull xs[MROWS][KCHUNK];   // duplicated {x,x} pairs

    int g   = blockIdx.y;          // 0..15 row group
    int kc  = blockIdx.x & 15;
    int nb  = blockIdx.x >> 4;     // 0..1
    int tid = threadIdx.x;
    int n   = nb * 512 + tid * 4;

    const float* X;
    int xrow, woff, secrow;
    if (g < 6)       { X = ent; xrow = g * 8;        woff = 0;     secrow = g * 8; }
    else if (g < 12) { X = ent; xrow = (g - 6) * 8;  woff = 2 * H; secrow = 48 + (g - 6) * 8; }
    else             { X = rel; xrow = (g - 12) * 8; woff = H;     secrow = 96 + (g - 12) * 8; }

    const int k0 = kc * KCHUNK;
    const float* wbase = W1 + (size_t)(woff + k0) * H + n;

    ulonglong2 wc[4];
#pragma unroll
    for (int r = 0; r < 4; r++)
        wc[r] = *(const ulonglong2*)(wbase + (size_t)r * H);

#pragma unroll
    for (int t = 0; t < 4; t++) {
        int idx = tid + t * 128;
        int m  = idx >> 6;
        int kk = idx & 63;
        float v = X[(size_t)(xrow + m) * H + k0 + kk];
        xs[m][kk] = f2pack(v, v);
    }
    __syncthreads();

    ull acc[MROWS][2];
#pragma unroll
    for (int m = 0; m < MROWS; m++) { acc[m][0] = 0ull; acc[m][1] = 0ull; }

#pragma unroll
    for (int b = 0; b < KCHUNK / 4; b++) {
        ulonglong2 wn[4];
        if (b < KCHUNK / 4 - 1) {
#pragma unroll
            for (int r = 0; r < 4; r++)
                wn[r] = *(const ulonglong2*)(wbase + (size_t)((b + 1) * 4 + r) * H);
        }
        int kk = b * 4;
#pragma unroll
        for (int m = 0; m < MROWS; m++) {
            ulonglong2 xa = *(const ulonglong2*)&xs[m][kk];
            ulonglong2 xb = *(const ulonglong2*)&xs[m][kk + 2];
            acc[m][0] = f2fma(xa.x, wc[0].x, acc[m][0]);
            acc[m][1] = f2fma(xa.x, wc[0].y, acc[m][1]);
            acc[m][0] = f2fma(xa.y, wc[1].x, acc[m][0]);
            acc[m][1] = f2fma(xa.y, wc[1].y, acc[m][1]);
            acc[m][0] = f2fma(xb.x, wc[2].x, acc[m][0]);
            acc[m][1] = f2fma(xb.x, wc[2].y, acc[m][1]);
            acc[m][0] = f2fma(xb.y, wc[3].x, acc[m][0]);
            acc[m][1] = f2fma(xb.y, wc[3].y, acc[m][1]);
        }
#pragma unroll
        for (int r = 0; r < 4; r++) wc[r] = wn[r];
    }

    float* dst = g_part + (size_t)kc * (TOTROWS * H) + (size_t)secrow * H + n;
#pragma unroll
    for (int m = 0; m < MROWS; m++) {
        ulonglong2 v; v.x = acc[m][0]; v.y = acc[m][1];
        *(ulonglong2*)(dst + (size_t)m * H) = v;
    }
}

// ---------------------------------------------------------------------------
// Kernel 2: reduce partials; fold b1 into P section; also emit transposed B.
// ---------------------------------------------------------------------------
__global__ void __launch_bounds__(256)
reduce_kernel(const float* __restrict__ b1v)
{
    int idx4 = blockIdx.x * 256 + threadIdx.x;   // < 32768
    const float4* part4 = (const float4*)g_part;
    float4 s = part4[idx4];
#pragma unroll
    for (int c = 1; c < KC; c++) {
        float4 p = part4[(size_t)c * 32768 + idx4];
        s.x += p.x; s.y += p.y; s.z += p.z; s.w += p.w;
    }
    if (idx4 < 48 * 256) {   // P section: fold b1
        float4 bb = ((const float4*)b1v)[idx4 & 255];
        s.x += bb.x; s.y += bb.y; s.z += bb.z; s.w += bb.w;
    }
    ((float4*)g_PQB)[idx4] = s;

    if (idx4 >= 96 * 256) {  // B section: also write transposed copy
        int rowB = (idx4 >> 8) - 96;   // relation k, 0..31
        int h4   = idx4 & 255;
        g_BT4[h4 * R + rowB] = s;
    }
}

// ---------------------------------------------------------------------------
// Kernel 2b: prep. Block 0 builds 8-j items; blocks 1..148 zero the output
// (active entries overwritten by score; deterministic).
// ---------------------------------------------------------------------------
__global__ void __launch_bounds__(256)
prep_kernel(const int* __restrict__ starts,
            const int* __restrict__ maxd_p,
            float* __restrict__ out)
{
    if (blockIdx.x == 0) {
        __shared__ int cnt[E], off[E];
        int t = threadIdx.x;
        int maxd = maxd_p[0];
        if (t < E) {
            int si = starts[t];
            int c = 0;
#pragma unroll 1
            for (int j = 0; j < E; j++) {
                int d = si - starts[j]; if (d < 0) d = -d;
                if (j != t && d <= maxd) c++;
            }
            cnt[t] = (c + 7) >> 3;   // items of 8
        }
        __syncthreads();
        if (t == 0) {
            int run = 0;
#pragma unroll 1
            for (int i = 0; i < E; i++) { off[i] = run; run += cnt[i]; }
            g_nitems = run;
        }
        __syncthreads();
        if (t < E) {
            int si = starts[t];
            int base = off[t];
            ull jp = 0; int nb = 0, p = 0; int first = 0;
#pragma unroll 1
            for (int j = 0; j < E; j++) {
                int d = si - starts[j]; if (d < 0) d = -d;
                if (j != t && d <= maxd) {
                    if (nb == 0) first = j;
                    jp |= (ull)j << (8 * nb);
                    nb++;
                    if (nb == 8) {
                        g_itemhdr[base + p] = t | (8 << 8);
                        g_itemjs[base + p] = jp;
                        p++; nb = 0; jp = 0;
                    }
                }
            }
            if (nb > 0) {   // pad remaining slots with the group's first j
                for (int s = nb; s < 8; s++)
                    jp |= (ull)first << (8 * s);
                g_itemhdr[base + p] = t | (nb << 8);
                g_itemjs[base + p] = jp;
            }
        }
    } else {
        int idx = (blockIdx.x - 1) * 256 + threadIdx.x;   // < 37888
        if (idx < E * E * R / 2) {
            out[idx] = 0.f;
            out[idx + E * E * R / 2] = 0.f;
        }
    }
}

// ---------------------------------------------------------------------------
// Kernel 3: scores. grid = 296 x 256 thr (2 blocks/SM, one wave for typical
// ~180 items). 8 warps; warp w owns h in [128w, 128w+128), lane = relation k.
// Per item (i + 8 j's): stage D[js][h] = P'(i)+Q(j) in smem (32 KB); inner
// loop: per-lane LDG.128 of BT4 + uniform LDG of W2 amortized over 8 j of
// LDS-broadcast D; packed f2 math, scalar relu on aliased halves.
// ---------------------------------------------------------------------------
__global__ void __launch_bounds__(256)
score_kernel(const float* __restrict__ W2,
             const float* __restrict__ b2v,
             float* __restrict__ out)
{
    __shared__ __align__(16) float Dsm[8][H];    // 32 KB
    __shared__ float psum[8][8][32];             // 8 KB

    int tid  = threadIdx.x;
    int lane = tid & 31;
    int w    = tid >> 5;
    float b2 = b2v[0];
    int nit  = g_nitems;

    const float4* PQB4 = (const float4*)g_PQB;
    const float4* W24  = (const float4*)W2;

#pragma unroll 1
    for (int item = blockIdx.x; item < nit; item += gridDim.x) {
        int hdr = g_itemhdr[item];
        int i   = hdr & 255;
        int nj  = hdr >> 8;
        ull jp  = g_itemjs[item];

        // stage D: 8 js x 256 float4 = 2048, 8 per thread
#pragma unroll
        for (int s = 0; s < 8; s++) {
            int idx = tid + s * 256;
            int js  = idx >> 8;
            int h4  = idx & 255;
            int j   = (int)((jp >> (8 * js)) & 63);
            float4 p = PQB4[(size_t)i * 256 + h4];
            float4 q = PQB4[(size_t)(E + j) * 256 + h4];
            float4 dv;
            dv.x = p.x + q.x; dv.y = p.y + q.y; dv.z = p.z + q.z; dv.w = p.w + q.w;
            ((float4*)Dsm[js])[h4] = dv;
        }
        __syncthreads();

        ull a01[8], a23[8];
#pragma unroll
        for (int jj = 0; jj < 8; jj++) { a01[jj] = 0ull; a23[jj] = 0ull; }

#pragma unroll 4
        for (int t = 0; t < 32; t++) {
            int h4 = w * 32 + t;
            ulonglong2 bv = *(const ulonglong2*)(g_BT4 + h4 * R + lane);  // B[k][4h]
            float4 wv = W24[h4];   // uniform, L1-hot
            ull w01 = f2pack(wv.x, wv.y), w23 = f2pack(wv.z, wv.w);
#pragma unroll
            for (int jj = 0; jj < 8; jj++) {
                ulonglong2 dv = *(const ulonglong2*)&Dsm[jj][h4 * 4];   // broadcast
                ull m01 = f2relu(f2add(dv.x, bv.x));
                ull m23 = f2relu(f2add(dv.y, bv.y));
                a01[jj] = f2fma(m01, w01, a01[jj]);
                a23[jj] = f2fma(m23, w23, a23[jj]);
            }
        }
#pragma unroll
        for (int jj = 0; jj < 8; jj++) {
            float r0, r1, r2, r3;
            f2unpack(a01[jj], r0, r1);
            f2unpack(a23[jj], r2, r3);
            psum[w][jj][lane] = (r0 + r1) + (r2 + r3);
        }
        __syncthreads();

        {
            int js = tid >> 5;   // 0..7
            if (js < nj) {
                int k = tid & 31;
                float s = 0.f;
#pragma unroll
                for (int ww = 0; ww < 8; ww++) s += psum[ww][js][k];
                int j = (int)((jp >> (8 * js)) & 63);
                float x = s + b2;
                out[((size_t)i * E + j) * R + k] = 1.0f / (1.0f + __expf(-x));
            }
        }
        __syncthreads();   // protect Dsm/psum before next item
    }
}

// ---------------------------------------------------------------------------
// Inputs (metadata order):
//  0 entity_emb f32[48,1024]  1 rel_emb f32[32,1024]  2 W1 f32[3072,1024]
//  3 b1 f32[1024]  4 W2 f32[1024,1]  5 b2 f32[1]
//  6 entity_starts i32[48]    7 max_distance i32
// Output: f32 [48,48,32]
// ---------------------------------------------------------------------------
extern "C" void kernel_launch(void* const* d_in, const int* in_sizes, int n_in,
                              void* d_out, int out_size)
{
    const float* ent    = (const float*)d_in[0];
    const float* rel    = (const float*)d_in[1];
    const float* W1     = (const float*)d_in[2];
    const float* b1     = (const float*)d_in[3];
    const float* W2     = (const float*)d_in[4];
    const float* b2     = (const float*)d_in[5];
    const int*   starts = (const int*)  d_in[6];
    const int*   maxd   = (const int*)  d_in[7];
    float* out = (float*)d_out;

    prep_kernel<<<149, 256>>>(starts, maxd, out);
    precompute_kernel<<<dim3(32, 16), 128>>>(ent, rel, W1);
    reduce_kernel<<<128, 256>>>(b1);
    score_kernel<<<296, 256>>>(W2, b2, out);
}

// round 14
// speedup vs baseline: 1.2050x; 1.2050x over previous
#include <cuda_runtime.h>
#include <math.h>

#define H 1024
#define E 48
#define R 32
#define KC 16          // k-chunks in precompute
#define KCHUNK 64      // H / KC
#define TOTROWS 128    // 48 P + 48 Q + 32 B rows
#define MROWS 8        // rows per precompute block
#define SLICEJ 8       // j per score block
#define NSLICE 6       // 48 / SLICEJ

typedef unsigned long long ull;

// Combined precompute result: [0:48H) = P+b1 rows, [48H:96H) = Q rows, [96H:128H) = B rows
__device__ __align__(16) float g_PQB[TOTROWS * H];
// Per-k-chunk partials (8 MB)
__device__ __align__(16) float g_part[KC * TOTROWS * H];
// B transposed for lane=k access: BT4[h4][k] = float4{B[k][4h4..4h4+3]}
__device__ __align__(16) float4 g_BT4[(H / 4) * R];

// ---- packed f32x2 helpers (Blackwell) ------------------------------------
__device__ __forceinline__ ull f2fma(ull a, ull b, ull c) {
    ull d;
    asm("fma.rn.f32x2 %0, %1, %2, %3;" : "=l"(d) : "l"(a), "l"(b), "l"(c));
    return d;
}
__device__ __forceinline__ ull f2add(ull a, ull b) {
    ull d;
    asm("add.rn.f32x2 %0, %1, %2;" : "=l"(d) : "l"(a), "l"(b));
    return d;
}
__device__ __forceinline__ ull f2pack(float lo, float hi) {
    ull d;
    asm("mov.b64 %0, {%1, %2};" : "=l"(d) : "f"(lo), "f"(hi));
    return d;
}
__device__ __forceinline__ void f2unpack(ull v, float& lo, float& hi) {
    asm("mov.b64 {%0, %1}, %2;" : "=f"(lo), "=f"(hi) : "l"(v));
}

// ---------------------------------------------------------------------------
// Kernel 1: partial GEMMs with depth-2 W prefetch (3 compile-time slots).
// grid = (32, 16): x = kc(16) + 16*nb(2 panels of 512 cols); y = 16 row-groups.
// 128 threads; thread owns 4 output columns, 8 rows. While batch b computes,
// batches b+1 and b+2's W loads (8 LDG.128/warp outstanding) are in flight —
// W1 is DRAM-cold by construction (read exactly once), so MLP=8 halves the
// exposed latency vs the old distance-1 prefetch.
// ---------------------------------------------------------------------------
struct WSlot { ulonglong2 r[4]; };

__device__ __forceinline__ void w_load(WSlot& s, const float* wbase, int batch) {
#pragma unroll
    for (int r = 0; r < 4; r++)
        s.r[r] = *(const ulonglong2*)(wbase + (size_t)(batch * 4 + r) * H);
}

__device__ __forceinline__ void w_consume(
    const WSlot& s, const ull* xrow, ull* acc0, ull* acc1, int m)
{
    ulonglong2 xa = *(const ulonglong2*)&xrow[0];   // k, k+1 (dup pairs)
    ulonglong2 xb = *(const ulonglong2*)&xrow[2];   // k+2, k+3
    ull a0 = acc0[m], a1 = acc1[m];
    a0 = f2fma(xa.x, s.r[0].x, a0);
    a1 = f2fma(xa.x, s.r[0].y, a1);
    a0 = f2fma(xa.y, s.r[1].x, a0);
    a1 = f2fma(xa.y, s.r[1].y, a1);
    a0 = f2fma(xb.x, s.r[2].x, a0);
    a1 = f2fma(xb.x, s.r[2].y, a1);
    a0 = f2fma(xb.y, s.r[3].x, a0);
    a1 = f2fma(xb.y, s.r[3].y, a1);
    acc0[m] = a0; acc1[m] = a1;
}

__global__ void __launch_bounds__(128)
precompute_kernel(const float* __restrict__ ent,
                  const float* __restrict__ rel,
                  const float* __restrict__ W1)
{
    __shared__ __align__(16) ull xs[MROWS][KCHUNK];   // duplicated {x,x} pairs

    int g   = blockIdx.y;          // 0..15 row group
    int kc  = blockIdx.x & 15;
    int nb  = blockIdx.x >> 4;     // 0..1
    int tid = threadIdx.x;
    int n   = nb * 512 + tid * 4;

    const float* X;
    int xrow, woff, secrow;
    if (g < 6)       { X = ent; xrow = g * 8;        woff = 0;     secrow = g * 8; }
    else if (g < 12) { X = ent; xrow = (g - 6) * 8;  woff = 2 * H; secrow = 48 + (g - 6) * 8; }
    else             { X = rel; xrow = (g - 12) * 8; woff = H;     secrow = 96 + (g - 12) * 8; }

    const int k0 = kc * KCHUNK;
    const float* wbase = W1 + (size_t)(woff + k0) * H + n;

    // prologue: batches 0 and 1 in flight
    WSlot s0, s1, s2;
    w_load(s0, wbase, 0);
    w_load(s1, wbase, 1);

    // stage X chunk: 8*64 = 512 packed entries, 4 per thread
#pragma unroll
    for (int t = 0; t < 4; t++) {
        int idx = tid + t * 128;
        int m  = idx >> 6;
        int kk = idx & 63;
        float v = X[(size_t)(xrow + m) * H + k0 + kk];
        xs[m][kk] = f2pack(v, v);
    }
    __syncthreads();

    ull acc0[MROWS], acc1[MROWS];
#pragma unroll
    for (int m = 0; m < MROWS; m++) { acc0[m] = 0ull; acc1[m] = 0ull; }

    // 16 batches in 3-phase unrolled groups; slot indices compile-time fixed.
#pragma unroll
    for (int bg = 0; bg < 5; bg++) {
        int b = bg * 3;
        // phase 0: consume s0, refill into s2 (batch b+2 is already loaded as s2
        // from the previous group's phase 2 except for the very first group).
        if (b + 2 < 16) w_load(s2, wbase, b + 2);
#pragma unroll
        for (int m = 0; m < MROWS; m++) w_consume(s0, &xs[m][b * 4], acc0, acc1, m);
        // phase 1: consume s1, refill s0 with batch b+3
        if (b + 3 < 16) w_load(s0, wbase, b + 3);
#pragma unroll
        for (int m = 0; m < MROWS; m++) w_consume(s1, &xs[m][(b + 1) * 4], acc0, acc1, m);
        // phase 2: consume s2, refill s1 with batch b+4
        if (b + 4 < 16) w_load(s1, wbase, b + 4);
#pragma unroll
        for (int m = 0; m < MROWS; m++) w_consume(s2, &xs[m][(b + 2) * 4], acc0, acc1, m);
    }
    // tail: batch 15 sits in s0 (loaded at bg=4 phase 1: b+3 = 15)
#pragma unroll
    for (int m = 0; m < MROWS; m++) w_consume(s0, &xs[m][15 * 4], acc0, acc1, m);

    float* dst = g_part + (size_t)kc * (TOTROWS * H) + (size_t)secrow * H + n;
#pragma unroll
    for (int m = 0; m < MROWS; m++) {
        ulonglong2 v; v.x = acc0[m]; v.y = acc1[m];
        *(ulonglong2*)(dst + (size_t)m * H) = v;
    }
}

// ---------------------------------------------------------------------------
// Kernel 2: reduce partials; fold b1 into P section; also emit transposed B.
// ---------------------------------------------------------------------------
__global__ void __launch_bounds__(256)
reduce_kernel(const float* __restrict__ b1v)
{
    int idx4 = blockIdx.x * 256 + threadIdx.x;   // < 32768
    const float4* part4 = (const float4*)g_part;
    float4 s = part4[idx4];
#pragma unroll
    for (int c = 1; c < KC; c++) {
        float4 p = part4[(size_t)c * 32768 + idx4];
        s.x += p.x; s.y += p.y; s.z += p.z; s.w += p.w;
    }
    if (idx4 < 48 * 256) {   // P section: fold b1
        float4 bb = ((const float4*)b1v)[idx4 & 255];
        s.x += bb.x; s.y += bb.y; s.z += bb.z; s.w += bb.w;
    }
    ((float4*)g_PQB)[idx4] = s;

    if (idx4 >= 96 * 256) {  // B section: also write transposed copy
        int rowB = (idx4 >> 8) - 96;   // relation k, 0..31
        int h4   = idx4 & 255;
        g_BT4[h4 * R + rowB] = s;
    }
}

// ---------------------------------------------------------------------------
// Kernel 3: scores, lane = relation (R6 winner, verbatim).
// grid = (NSLICE, 48): y = i, x = slice of 8 j. 256 threads = 8 warps;
// warp w owns h in [128w, 128w+128). B via per-lane LDG.128 of g_BT4,
// D/W2 via LDS broadcast. Cross-warp reduce via psum smem.
// ---------------------------------------------------------------------------
__global__ void __launch_bounds__(256)
score_kernel(const float* __restrict__ W2,
             const float* __restrict__ b2v,
             const int*   __restrict__ starts,
             const int*   __restrict__ maxd_p,
             float*       __restrict__ out)
{
    __shared__ __align__(16) float Dsm[SLICEJ][H];   // 32 KB
    __shared__ __align__(16) float W2s[H];           // 4 KB
    __shared__ float psum[8][SLICEJ][32];            // 8 KB
    __shared__ int jl[SLICEJ];
    __shared__ int s_cnt;

    int i     = blockIdx.y;
    int slice = blockIdx.x;
    int j0    = slice * SLICEJ;
    int tid   = threadIdx.x;
    int lane  = tid & 31;
    int w     = tid >> 5;

    int si   = starts[i];
    int maxd = maxd_p[0];

    if (tid == 0) {
        int c = 0;
#pragma unroll
        for (int t = 0; t < SLICEJ; t++) {
            int j = j0 + t;
            int d = si - starts[j]; if (d < 0) d = -d;
            if (j != i && d <= maxd) jl[c++] = j;
        }
        s_cnt = c;
        for (int t = c; t < SLICEJ; t++) jl[t] = (c > 0) ? jl[0] : j0;
    }
    __syncthreads();
    int cnt = s_cnt;

    // zeros for inactive j in this slice
    for (int t = tid; t < SLICEJ * R; t += 256) {
        int jj = t >> 5, k = t & 31;
        int j = j0 + jj;
        int d = si - starts[j]; if (d < 0) d = -d;
        if (!((j != i) && (d <= maxd)))
            out[((size_t)i * E + j) * R + k] = 0.f;
    }
    if (cnt == 0) return;

    int ng   = (cnt + 3) >> 2;
    int npad = ng * 4;

    // stage W2
    for (int t = tid; t < H / 4; t += 256)
        ((float4*)W2s)[t] = ((const float4*)W2)[t];

    // stage D[jslot][h] = P'(i)[h] + Q(j)[h] (padded jslots use jl[0])
    for (int idx = tid; idx < npad * (H / 4); idx += 256) {
        int js = idx >> 8;        // H/4 = 256
        int h4 = idx & 255;
        int j  = jl[js];
        float4 p = ((const float4*)g_PQB)[(size_t)i * (H / 4) + h4];
        float4 q = ((const float4*)g_PQB)[(size_t)(E + j) * (H / 4) + h4];
        float4 dv;
        dv.x = p.x + q.x; dv.y = p.y + q.y; dv.z = p.z + q.z; dv.w = p.w + q.w;
        ((float4*)Dsm[js])[h4] = dv;
    }
    __syncthreads();

#pragma unroll 1
    for (int g = 0; g < ng; g++) {
        ull a01[4], a23[4];
#pragma unroll
        for (int jj = 0; jj < 4; jj++) { a01[jj] = 0ull; a23[jj] = 0ull; }

#pragma unroll 4
        for (int t = 0; t < 32; t++) {
            int h4 = w * 32 + t;
            float4 b  = g_BT4[h4 * R + lane];           // per-lane B[k][4h]
            float4 wv = ((const float4*)W2s)[h4];       // broadcast
            ull b01 = f2pack(b.x, b.y),  b23 = f2pack(b.z, b.w);
            ull w01 = f2pack(wv.x, wv.y), w23 = f2pack(wv.z, wv.w);
#pragma unroll
            for (int jj = 0; jj < 4; jj++) {
                float4 dv = ((const float4*)Dsm[g * 4 + jj])[h4];  // broadcast
                ull s01 = f2add(b01, f2pack(dv.x, dv.y));
                ull s23 = f2add(b23, f2pack(dv.z, dv.w));
                float t0, t1, t2, t3;
                f2unpack(s01, t0, t1);
                f2unpack(s23, t2, t3);
                t0 = fmaxf(t0, 0.f); t1 = fmaxf(t1, 0.f);
                t2 = fmaxf(t2, 0.f); t3 = fmaxf(t3, 0.f);
                a01[jj] = f2fma(f2pack(t0, t1), w01, a01[jj]);
                a23[jj] = f2fma(f2pack(t2, t3), w23, a23[jj]);
            }
        }
#pragma unroll
        for (int jj = 0; jj < 4; jj++) {
            float r0, r1, r2, r3;
            f2unpack(a01[jj], r0, r1);
            f2unpack(a23[jj], r2, r3);
            psum[w][g * 4 + jj][lane] = (r0 + r1) + (r2 + r3);
        }
    }
    __syncthreads();

    // cross-warp reduce + sigmoid + store (active jslots only)
    float b2 = b2v[0];
    for (int t = tid; t < cnt * R; t += 256) {
        int js = t >> 5, k = t & 31;
        float s = 0.f;
#pragma unroll
        for (int ww = 0; ww < 8; ww++) s += psum[ww][js][k];
        float x = s + b2;
        out[((size_t)i * E + jl[js]) * R + k] = 1.0f / (1.0f + __expf(-x));
    }
}

// ---------------------------------------------------------------------------
// Inputs (metadata order):
//  0 entity_emb f32[48,1024]  1 rel_emb f32[32,1024]  2 W1 f32[3072,1024]
//  3 b1 f32[1024]  4 W2 f32[1024,1]  5 b2 f32[1]
//  6 entity_starts i32[48]    7 max_distance i32
// Output: f32 [48,48,32]
// ---------------------------------------------------------------------------
extern "C" void kernel_launch(void* const* d_in, const int* in_sizes, int n_in,
                              void* d_out, int out_size)
{
    const float* ent    = (const float*)d_in[0];
    const float* rel    = (const float*)d_in[1];
    const float* W1     = (const float*)d_in[2];
    const float* b1     = (const float*)d_in[3];
    const float* W2     = (const float*)d_in[4];
    const float* b2     = (const float*)d_in[5];
    const int*   starts = (const int*)  d_in[6];
    const int*   maxd   = (const int*)  d_in[7];
    float* out = (float*)d_out;

    precompute_kernel<<<dim3(32, 16), 128>>>(ent, rel, W1);
    reduce_kernel<<<128, 256>>>(b1);
    score_kernel<<<dim3(NSLICE, E), 256>>>(W2, b2, starts, maxd, out);
}